// round 12
// baseline (speedup 1.0000x reference)
#include <cuda_runtime.h>
#include <cuda_bf16.h>
#include <cstdint>

// Shapes
#define B_DIM 2048
#define N_Z 8
#define NOISE 32
#define STATE 1024
#define HID 1024
#define EPI_H 512
#define PRIOR_H 5
#define PRI_N 160   // 32 ensembles * 5
#define KTOT 2048   // xf concat length

typedef unsigned long long u64;

// ---- f32x2 helpers (prior gemm) ----
__device__ __forceinline__ u64 pk2(float lo, float hi) {
    u64 r; asm("mov.b64 %0,{%1,%2};" : "=l"(r) : "f"(lo), "f"(hi)); return r;
}
__device__ __forceinline__ u64 fma2(u64 a, u64 b, u64 c) {
    u64 d; asm("fma.rn.f32x2 %0,%1,%2,%3;" : "=l"(d) : "l"(a), "l"(b), "l"(c)); return d;
}
__device__ __forceinline__ float2 unpk(u64 v) {
    float2 r; asm("mov.b64 {%0,%1},%2;" : "=f"(r.x), "=f"(r.y) : "l"(v)); return r;
}

__device__ __forceinline__ uint32_t smem_u32(const void* p) {
    uint32_t a;
    asm("{ .reg .u64 t; cvta.to.shared.u64 t, %1; cvt.u32.u64 %0, t; }" : "=r"(a) : "l"(p));
    return a;
}

// ---- cp.async ----
#define CP16(dst, src) \
    asm volatile("cp.async.cg.shared.global [%0], [%1], 16;" :: "r"(dst), "l"(src))
#define CP_COMMIT() asm volatile("cp.async.commit_group;" ::: "memory")
#define CP_WAIT1() asm volatile("cp.async.wait_group 1;" ::: "memory")

// ---- Scratch (no allocation allowed) ----
__device__ float g_H[B_DIM * EPI_H];
__device__ float g_P1[B_DIM * PRI_N];
__device__ float g_W1r[STATE * PRI_N];
__device__ __align__(16) __nv_bfloat16 g_Ahi[B_DIM * KTOT];   // 8 MB
__device__ __align__(16) __nv_bfloat16 g_Alo[B_DIM * KTOT];   // 8 MB
__device__ __align__(16) __nv_bfloat16 g_Bhi[EPI_H * KTOT];   // 2 MB, [n][k]
__device__ __align__(16) __nv_bfloat16 g_Blo[EPI_H * KTOT];   // 2 MB

// ---------------------------------------------------------------------------
// Prep: split A = [x|feature] into bf16 hi/lo, row-major [2048][2048]
// ---------------------------------------------------------------------------
__global__ __launch_bounds__(256) void convert_split_A(
    const float* __restrict__ X, const float* __restrict__ F) {
    int i4 = blockIdx.x * 256 + threadIdx.x;
    int row = i4 >> 9;
    int c4 = i4 & 511;
    const float* src = (c4 < 256) ? (X + row * 1024 + c4 * 4)
                                  : (F + row * 1024 + (c4 - 256) * 4);
    float4 v = *(const float4*)src;
    __nv_bfloat16 h0 = __float2bfloat16_rn(v.x), h1 = __float2bfloat16_rn(v.y);
    __nv_bfloat16 h2 = __float2bfloat16_rn(v.z), h3 = __float2bfloat16_rn(v.w);
    __nv_bfloat16 l0 = __float2bfloat16_rn(v.x - __bfloat162float(h0));
    __nv_bfloat16 l1 = __float2bfloat16_rn(v.y - __bfloat162float(h1));
    __nv_bfloat16 l2 = __float2bfloat16_rn(v.z - __bfloat162float(h2));
    __nv_bfloat16 l3 = __float2bfloat16_rn(v.w - __bfloat162float(h3));
    __nv_bfloat162 ph0 = __halves2bfloat162(h0, h1), ph1 = __halves2bfloat162(h2, h3);
    __nv_bfloat162 pl0 = __halves2bfloat162(l0, l1), pl1 = __halves2bfloat162(l2, l3);
    uint2 uh; uh.x = *(uint32_t*)&ph0; uh.y = *(uint32_t*)&ph1;
    uint2 ul; ul.x = *(uint32_t*)&pl0; ul.y = *(uint32_t*)&pl1;
    size_t off = (size_t)row * KTOT + c4 * 4;
    *(uint2*)(g_Ahi + off) = uh;
    *(uint2*)(g_Alo + off) = ul;
}

// ---------------------------------------------------------------------------
// Prep: transpose+split W[0:2048][512] -> Bhi/Blo [512][2048]
// ---------------------------------------------------------------------------
__global__ __launch_bounds__(256) void transpose_split_W(const float* __restrict__ W) {
    __shared__ float t[32][33];
    int kt = blockIdx.x;   // 64
    int nt = blockIdx.y;   // 16
    int tx = threadIdx.x;  // 32
    int ty = threadIdx.y;  // 8
#pragma unroll
    for (int i = 0; i < 4; i++)
        t[ty * 4 + i][tx] = W[(size_t)(kt * 32 + ty * 4 + i) * EPI_H + nt * 32 + tx];
    __syncthreads();
#pragma unroll
    for (int i = 0; i < 4; i++) {
        int n = nt * 32 + ty * 4 + i;
        int k = kt * 32 + tx;
        float v = t[tx][ty * 4 + i];
        __nv_bfloat16 h = __float2bfloat16_rn(v);
        __nv_bfloat16 l = __float2bfloat16_rn(v - __bfloat162float(h));
        g_Bhi[(size_t)n * KTOT + k] = h;
        g_Blo[(size_t)n * KTOT + k] = l;
    }
}

// ---------------------------------------------------------------------------
// Repack Wp1[32][1024][5] -> W1r[1024][160]
// ---------------------------------------------------------------------------
__global__ void repack_wp1(const float* __restrict__ Wp1) {
    int idx = blockIdx.x * 256 + threadIdx.x;
    if (idx < STATE * PRI_N) {
        int k = idx / PRI_N;
        int c = idx - k * PRI_N;
        int e = c / PRIOR_H;
        int h = c - e * PRIOR_H;
        g_W1r[idx] = Wp1[e * (STATE * PRIOR_H) + k * PRIOR_H + h];
    }
}

// ---------------------------------------------------------------------------
// Tensor-core GEMM (bf16 3-pass hi/lo split), mma.sync m16n8k16.
// BM=64 BN=64 BK=64, 128 threads (4 warps, warp tile 32x32), 3-stage cp.async,
// register-fragment double buffering + pass-major MMA ordering.
// ---------------------------------------------------------------------------
#define GM_BM 64
#define GM_BN 64
#define GM_BK 64
#define NKB (KTOT / GM_BK)    // 32
#define SM_AHI 0
#define SM_ALO 8192
#define SM_BHI 16384
#define SM_BLO 24576
#define STAGE_B 32768         // 32 KB per stage
#define NSTAGE 3              // 96 KB total
#define GM_THREADS 128

__device__ __forceinline__ uint32_t swz(int r, int c) {
    return (uint32_t)(r * 128 + ((c ^ (r & 7)) * 16));
}
__device__ __forceinline__ void ldmx4(uint32_t addr, uint32_t* r) {
    asm volatile("ldmatrix.sync.aligned.m8n8.x4.shared.b16 {%0,%1,%2,%3}, [%4];"
        : "=r"(r[0]), "=r"(r[1]), "=r"(r[2]), "=r"(r[3]) : "r"(addr));
}
__device__ __forceinline__ void mma16816(float* c, const uint32_t* a,
                                         uint32_t b0, uint32_t b1) {
    asm volatile("mma.sync.aligned.m16n8k16.row.col.f32.bf16.bf16.f32 "
        "{%0,%1,%2,%3},{%4,%5,%6,%7},{%8,%9},{%0,%1,%2,%3};"
        : "+f"(c[0]), "+f"(c[1]), "+f"(c[2]), "+f"(c[3])
        : "r"(a[0]), "r"(a[1]), "r"(a[2]), "r"(a[3]), "r"(b0), "r"(b1));
}

// issue one full stage of cp.async loads (16 chunks per thread)
__device__ __forceinline__ void issue_stage(uint32_t nb, int ko, int tid,
                                            int row0, int col0) {
#pragma unroll
    for (int i = 0; i < 4; i++) {
        int ch = tid + i * GM_THREADS;
        int r = ch >> 3, c = ch & 7;
        uint32_t o = swz(r, c);
        CP16(nb + SM_AHI + o, g_Ahi + (row0 + r) * KTOT + ko + c * 8);
        CP16(nb + SM_ALO + o, g_Alo + (row0 + r) * KTOT + ko + c * 8);
        CP16(nb + SM_BHI + o, g_Bhi + (col0 + r) * KTOT + ko + c * 8);
        CP16(nb + SM_BLO + o, g_Blo + (col0 + r) * KTOT + ko + c * 8);
    }
}

struct Frags {
    uint32_t ah[2][4], al[2][4], bh[2][4], bl[2][4];
};

__device__ __forceinline__ void load_frags(Frags& f, uint32_t bufb, int kblk,
                                           int wm, int wn, int lrow, int chbase) {
    const int ch = kblk * 2 + chbase;
#pragma unroll
    for (int mi = 0; mi < 2; mi++) {
        int r = wm * 32 + mi * 16 + lrow;
        uint32_t off = r * 128 + ((ch ^ (r & 7)) * 16);
        ldmx4(bufb + SM_AHI + off, f.ah[mi]);
        ldmx4(bufb + SM_ALO + off, f.al[mi]);
    }
#pragma unroll
    for (int ni = 0; ni < 2; ni++) {
        int r = wn * 32 + ni * 16 + lrow;
        uint32_t off = r * 128 + ((ch ^ (r & 7)) * 16);
        ldmx4(bufb + SM_BHI + off, f.bh[ni]);
        ldmx4(bufb + SM_BLO + off, f.bl[ni]);
    }
}

__device__ __forceinline__ void mma_all(float acc[2][4][4], const Frags& f) {
    // pass 1: Ahi x Bhi  (8 independent MMAs)
#pragma unroll
    for (int mi = 0; mi < 2; mi++)
#pragma unroll
        for (int ni = 0; ni < 2; ni++)
#pragma unroll
            for (int s = 0; s < 2; s++)
                mma16816(acc[mi][ni * 2 + s], f.ah[mi], f.bh[ni][s], f.bh[ni][s + 2]);
    // pass 2: Ahi x Blo
#pragma unroll
    for (int mi = 0; mi < 2; mi++)
#pragma unroll
        for (int ni = 0; ni < 2; ni++)
#pragma unroll
            for (int s = 0; s < 2; s++)
                mma16816(acc[mi][ni * 2 + s], f.ah[mi], f.bl[ni][s], f.bl[ni][s + 2]);
    // pass 3: Alo x Bhi
#pragma unroll
    for (int mi = 0; mi < 2; mi++)
#pragma unroll
        for (int ni = 0; ni < 2; ni++)
#pragma unroll
            for (int s = 0; s < 2; s++)
                mma16816(acc[mi][ni * 2 + s], f.al[mi], f.bh[ni][s], f.bh[ni][s + 2]);
}

__global__ __launch_bounds__(GM_THREADS, 2) void gemm_mma(const float* __restrict__ bias) {
    extern __shared__ char smem_raw[];
    const uint32_t sb = smem_u32(smem_raw);

    const int tid = threadIdx.x;
    const int lane = tid & 31;
    const int wid = tid >> 5;
    const int wm = wid & 1;        // 2 m-warps x 32 rows
    const int wn = wid >> 1;       // 2 n-warps x 32 cols
    const int row0 = blockIdx.y * GM_BM;
    const int col0 = blockIdx.x * GM_BN;
    const int lrow = lane & 15;
    const int chbase = lane >> 4;

    float acc[2][4][4];
#pragma unroll
    for (int mi = 0; mi < 2; mi++)
#pragma unroll
        for (int nf = 0; nf < 4; nf++)
#pragma unroll
            for (int q = 0; q < 4; q++) acc[mi][nf][q] = 0.f;

    // issue stages 0 and 1
    issue_stage(sb, 0, tid, row0, col0);
    CP_COMMIT();
    issue_stage(sb + STAGE_B, GM_BK, tid, row0, col0);
    CP_COMMIT();

    Frags fr[2];
    int slot = 0;
    for (int kb = 0; kb < NKB; kb++) {
        CP_WAIT1();
        __syncthreads();

        if (kb + 2 < NKB) {
            int s2 = slot + 2; if (s2 >= NSTAGE) s2 -= NSTAGE;
            issue_stage(sb + s2 * STAGE_B, (kb + 2) * GM_BK, tid, row0, col0);
        }
        CP_COMMIT();

        // ---- compute on slot: 4 kblk of k16, frag double-buffered ----
        const uint32_t bufb = sb + slot * STAGE_B;
        load_frags(fr[0], bufb, 0, wm, wn, lrow, chbase);
#pragma unroll
        for (int kblk = 0; kblk < 4; kblk++) {
            const int cur = kblk & 1;
            if (kblk < 3)
                load_frags(fr[cur ^ 1], bufb, kblk + 1, wm, wn, lrow, chbase);
            mma_all(acc, fr[cur]);
        }

        slot++; if (slot >= NSTAGE) slot = 0;
    }

    // ---- epilogue: add bias, store to g_H ----
#pragma unroll
    for (int mi = 0; mi < 2; mi++)
#pragma unroll
        for (int nf = 0; nf < 4; nf++) {
            int r = row0 + wm * 32 + mi * 16 + (lane >> 2);
            int cc = col0 + wn * 32 + nf * 8 + (lane & 3) * 2;
            float2 b2 = *(const float2*)(bias + cc);
            float2 v0, v1;
            v0.x = acc[mi][nf][0] + b2.x; v0.y = acc[mi][nf][1] + b2.y;
            v1.x = acc[mi][nf][2] + b2.x; v1.y = acc[mi][nf][3] + b2.y;
            *(float2*)(g_H + r * EPI_H + cc) = v0;
            *(float2*)(g_H + (r + 8) * EPI_H + cc) = v1;
        }
}

// ---------------------------------------------------------------------------
// Prior GEMM: g_P1[2048][160] = relu(x @ g_W1r + bp1)   (f32x2)
// ---------------------------------------------------------------------------
#define P_BM 64
#define P_BN 32
#define P_BK 16
__global__ __launch_bounds__(128) void sgemm_prior(
    const float* __restrict__ X, const float* __restrict__ bp1) {
    __shared__ float As[2][P_BK][P_BM + 4];
    __shared__ float Bs[2][P_BK][P_BN];

    const int tid = threadIdx.x;
    const int row0 = blockIdx.y * P_BM;
    const int col0 = blockIdx.x * P_BN;

    const int ar = tid >> 2;
    const int ac4 = tid & 3;
    const int bkr = tid >> 3;
    const int bjc = tid & 7;
    const int ty = tid >> 3;
    const int tx = tid & 7;

    u64 acc2[2][4];
#pragma unroll
    for (int i = 0; i < 2; i++)
#pragma unroll
        for (int j = 0; j < 4; j++) acc2[i][j] = 0ULL;

    float4 pa0, pa1, pb;
    {
        int k = ac4 * 4;
        pa0 = *(const float4*)(X + (row0 + ar) * STATE + k);
        pa1 = *(const float4*)(X + (row0 + ar + 32) * STATE + k);
        pb  = *(const float4*)(g_W1r + bkr * PRI_N + col0 + bjc * 4);
    }
    {
        As[0][ac4 * 4 + 0][ar] = pa0.x; As[0][ac4 * 4 + 1][ar] = pa0.y;
        As[0][ac4 * 4 + 2][ar] = pa0.z; As[0][ac4 * 4 + 3][ar] = pa0.w;
        As[0][ac4 * 4 + 0][ar + 32] = pa1.x; As[0][ac4 * 4 + 1][ar + 32] = pa1.y;
        As[0][ac4 * 4 + 2][ar + 32] = pa1.z; As[0][ac4 * 4 + 3][ar + 32] = pa1.w;
        *(float4*)&Bs[0][bkr][bjc * 4] = pb;
    }
    __syncthreads();

    const int NT = STATE / P_BK;
    int buf = 0;
    for (int kt = 0; kt < NT; kt++) {
        if (kt + 1 < NT) {
            int kg = (kt + 1) * P_BK + ac4 * 4;
            pa0 = *(const float4*)(X + (row0 + ar) * STATE + kg);
            pa1 = *(const float4*)(X + (row0 + ar + 32) * STATE + kg);
            pb  = *(const float4*)(g_W1r + ((kt + 1) * P_BK + bkr) * PRI_N + col0 + bjc * 4);
        }
#pragma unroll
        for (int kk = 0; kk < P_BK; kk++) {
            ulonglong2 aa = *(const ulonglong2*)&As[buf][kk][ty * 4];
            float4 rb = *(const float4*)&Bs[buf][kk][tx * 4];
            u64 a2[2] = {aa.x, aa.y};
            u64 bd[4];
            bd[0] = pk2(rb.x, rb.x); bd[1] = pk2(rb.y, rb.y);
            bd[2] = pk2(rb.z, rb.z); bd[3] = pk2(rb.w, rb.w);
#pragma unroll
            for (int i = 0; i < 2; i++)
#pragma unroll
                for (int j = 0; j < 4; j++)
                    acc2[i][j] = fma2(a2[i], bd[j], acc2[i][j]);
        }
        if (kt + 1 < NT) {
            int nb = buf ^ 1;
            As[nb][ac4 * 4 + 0][ar] = pa0.x; As[nb][ac4 * 4 + 1][ar] = pa0.y;
            As[nb][ac4 * 4 + 2][ar] = pa0.z; As[nb][ac4 * 4 + 3][ar] = pa0.w;
            As[nb][ac4 * 4 + 0][ar + 32] = pa1.x; As[nb][ac4 * 4 + 1][ar + 32] = pa1.y;
            As[nb][ac4 * 4 + 2][ar + 32] = pa1.z; As[nb][ac4 * 4 + 3][ar + 32] = pa1.w;
            *(float4*)&Bs[nb][bkr][bjc * 4] = pb;
        }
        __syncthreads();
        buf ^= 1;
    }

    float4 bv = *(const float4*)(bp1 + col0 + tx * 4);
#pragma unroll
    for (int i2 = 0; i2 < 2; i2++) {
        float2 u0 = unpk(acc2[i2][0]), u1 = unpk(acc2[i2][1]);
        float2 u2 = unpk(acc2[i2][2]), u3 = unpk(acc2[i2][3]);
        int r = row0 + ty * 4 + 2 * i2;
        float4 olo, ohi;
        olo.x = fmaxf(u0.x + bv.x, 0.f); olo.y = fmaxf(u1.x + bv.y, 0.f);
        olo.z = fmaxf(u2.x + bv.z, 0.f); olo.w = fmaxf(u3.x + bv.w, 0.f);
        ohi.x = fmaxf(u0.y + bv.x, 0.f); ohi.y = fmaxf(u1.y + bv.y, 0.f);
        ohi.z = fmaxf(u2.y + bv.z, 0.f); ohi.w = fmaxf(u3.y + bv.w, 0.f);
        *(float4*)(g_P1 + r * PRI_N + col0 + tx * 4) = olo;
        *(float4*)(g_P1 + (r + 1) * PRI_N + col0 + tx * 4) = ohi;
    }
}

// ---------------------------------------------------------------------------
// Fused epilogue (R2/R6 form, measured 52.3us)
// ---------------------------------------------------------------------------
__global__ __launch_bounds__(512, 1) void epilogue_kernel(
    const float* __restrict__ Z, const float* __restrict__ Wep1,
    const float* __restrict__ Wep2, const float* __restrict__ bep2,
    const float* __restrict__ Wp2, const float* __restrict__ bp2,
    const float* __restrict__ Wp3, const float* __restrict__ bp3,
    float* __restrict__ out) {
    __shared__ __align__(16) float sZ[N_Z * NOISE];
    __shared__ float sP[NOISE];
    __shared__ float sRed[16][N_Z];

    const int tid = threadIdx.x;
    const int j = tid;
    const int lane = tid & 31;
    const int warp = tid >> 5;
    const int b0 = blockIdx.x * 8;

    float w1z[NOISE];
    float w2t[NOISE];
#pragma unroll
    for (int k = 0; k < NOISE; k++)
        w1z[k] = Wep1[(2048 + k) * EPI_H + j];
#pragma unroll
    for (int k4 = 0; k4 < NOISE / 4; k4++) {
        float4 v = *(const float4*)(Wep2 + j * NOISE + k4 * 4);
        w2t[k4 * 4 + 0] = v.x; w2t[k4 * 4 + 1] = v.y;
        w2t[k4 * 4 + 2] = v.z; w2t[k4 * 4 + 3] = v.w;
    }

    for (int bi = 0; bi < 8; bi++) {
        const int b = b0 + bi;
        const float Hj = g_H[b * EPI_H + j];

        if (tid >= 256) {
            int t = tid - 256;
            sZ[t] = Z[b * (N_Z * NOISE) + t];
        } else if (tid < 32) {
            int e = tid;
            const float* p1 = g_P1 + b * PRI_N + e * PRIOR_H;
            float h1[PRIOR_H];
#pragma unroll
            for (int h = 0; h < PRIOR_H; h++) h1[h] = p1[h];
            float h2[PRIOR_H];
#pragma unroll
            for (int g = 0; g < PRIOR_H; g++) {
                float s = bp2[e * PRIOR_H + g];
#pragma unroll
                for (int h = 0; h < PRIOR_H; h++)
                    s = fmaf(h1[h], Wp2[e * 25 + h * PRIOR_H + g], s);
                h2[g] = fmaxf(s, 0.f);
            }
            float p = bp3[e];
#pragma unroll
            for (int g = 0; g < PRIOR_H; g++)
                p = fmaf(h2[g], Wp3[e * PRIOR_H + g], p);
            sP[e] = p + bep2[e];
        }
        __syncthreads();

        float part[N_Z];
#pragma unroll
        for (int n = 0; n < N_Z; n++) {
            float hz = 0.f, wz = 0.f;
            const float4* z4 = (const float4*)(sZ + n * NOISE);
#pragma unroll
            for (int k4 = 0; k4 < NOISE / 4; k4++) {
                float4 zv = z4[k4];
                int k = k4 * 4;
                hz = fmaf(zv.x, w1z[k + 0], hz); wz = fmaf(zv.x, w2t[k + 0], wz);
                hz = fmaf(zv.y, w1z[k + 1], hz); wz = fmaf(zv.y, w2t[k + 1], wz);
                hz = fmaf(zv.z, w1z[k + 2], hz); wz = fmaf(zv.z, w2t[k + 2], wz);
                hz = fmaf(zv.w, w1z[k + 3], hz); wz = fmaf(zv.w, w2t[k + 3], wz);
            }
            float h = fmaxf(Hj + hz, 0.f);
            part[n] = h * wz;
        }

#pragma unroll
        for (int n = 0; n < N_Z; n++) {
            float v = part[n];
            v += __shfl_xor_sync(0xffffffffu, v, 16);
            v += __shfl_xor_sync(0xffffffffu, v, 8);
            v += __shfl_xor_sync(0xffffffffu, v, 4);
            v += __shfl_xor_sync(0xffffffffu, v, 2);
            v += __shfl_xor_sync(0xffffffffu, v, 1);
            if (lane == 0) sRed[warp][n] = v;
        }
        __syncthreads();

        if (tid < N_Z) {
            float s = 0.f;
#pragma unroll
            for (int w = 0; w < 16; w++) s += sRed[w][tid];
            const float* zn = sZ + tid * NOISE;
#pragma unroll
            for (int e = 0; e < NOISE; e++) s = fmaf(sP[e], zn[e], s);
            out[b * N_Z + tid] = s;
        }
        __syncthreads();
    }
}

// ---------------------------------------------------------------------------
extern "C" void kernel_launch(void* const* d_in, const int* in_sizes, int n_in,
                              void* d_out, int out_size) {
    const float* x    = (const float*)d_in[0];
    const float* feat = (const float*)d_in[1];
    const float* z    = (const float*)d_in[2];
    const float* Wep1 = (const float*)d_in[3];
    const float* bep1 = (const float*)d_in[4];
    const float* Wep2 = (const float*)d_in[5];
    const float* bep2 = (const float*)d_in[6];
    const float* Wp1  = (const float*)d_in[7];
    const float* bp1  = (const float*)d_in[8];
    const float* Wp2  = (const float*)d_in[9];
    const float* bp2  = (const float*)d_in[10];
    const float* Wp3  = (const float*)d_in[11];
    const float* bp3  = (const float*)d_in[12];
    float* out = (float*)d_out;

    cudaFuncSetAttribute(gemm_mma, cudaFuncAttributeMaxDynamicSharedMemorySize,
                         NSTAGE * STAGE_B);

    convert_split_A<<<(B_DIM * KTOT / 4) / 256, 256>>>(x, feat);
    transpose_split_W<<<dim3(64, 16), dim3(32, 8)>>>(Wep1);
    repack_wp1<<<(STATE * PRI_N + 255) / 256, 256>>>(Wp1);
    gemm_mma<<<dim3(EPI_H / GM_BN, B_DIM / GM_BM), GM_THREADS, NSTAGE * STAGE_B>>>(bep1);
    sgemm_prior<<<dim3(PRI_N / P_BN, B_DIM / P_BM), 128>>>(x, bp1);
    epilogue_kernel<<<B_DIM / 8, 512>>>(z, Wep1, Wep2, bep2, Wp2, bp2, Wp3, bp3, out);
}

// round 14
// speedup vs baseline: 1.0983x; 1.0983x over previous
#include <cuda_runtime.h>
#include <cuda_bf16.h>
#include <cstdint>

// Shapes
#define B_DIM 2048
#define N_Z 8
#define NOISE 32
#define STATE 1024
#define HID 1024
#define EPI_H 512
#define PRIOR_H 5
#define PRI_N 160   // 32 ensembles * 5
#define KTOT 2048   // xf concat length
#define BN_TOT (B_DIM * N_Z)   // 16384

typedef unsigned long long u64;

// ---- f32x2 helpers (prior gemm) ----
__device__ __forceinline__ u64 pk2(float lo, float hi) {
    u64 r; asm("mov.b64 %0,{%1,%2};" : "=l"(r) : "f"(lo), "f"(hi)); return r;
}
__device__ __forceinline__ u64 fma2(u64 a, u64 b, u64 c) {
    u64 d; asm("fma.rn.f32x2 %0,%1,%2,%3;" : "=l"(d) : "l"(a), "l"(b), "l"(c)); return d;
}
__device__ __forceinline__ float2 unpk(u64 v) {
    float2 r; asm("mov.b64 {%0,%1},%2;" : "=f"(r.x), "=f"(r.y) : "l"(v)); return r;
}

__device__ __forceinline__ uint32_t smem_u32(const void* p) {
    uint32_t a;
    asm("{ .reg .u64 t; cvta.to.shared.u64 t, %1; cvt.u32.u64 %0, t; }" : "=r"(a) : "l"(p));
    return a;
}

// ---- cp.async ----
#define CP16(dst, src) \
    asm volatile("cp.async.cg.shared.global [%0], [%1], 16;" :: "r"(dst), "l"(src))
#define CP_COMMIT() asm volatile("cp.async.commit_group;" ::: "memory")
#define CP_WAIT1() asm volatile("cp.async.wait_group 1;" ::: "memory")

// ---- Scratch (no allocation allowed) ----
__device__ float g_H[B_DIM * EPI_H];
__device__ float g_P1[B_DIM * PRI_N];
__device__ float g_W1r[STATE * PRI_N];
__device__ __align__(16) __nv_bfloat16 g_Ahi[B_DIM * KTOT];   // 8 MB
__device__ __align__(16) __nv_bfloat16 g_Alo[B_DIM * KTOT];   // 8 MB
__device__ __align__(16) __nv_bfloat16 g_Bhi[EPI_H * KTOT];   // 2 MB
__device__ __align__(16) __nv_bfloat16 g_Blo[EPI_H * KTOT];   // 2 MB
__device__ __align__(16) __nv_bfloat16 g_Zhi[BN_TOT * NOISE]; // 1 MB
__device__ __align__(16) __nv_bfloat16 g_Zlo[BN_TOT * NOISE]; // 1 MB
__device__ __align__(16) __nv_bfloat16 g_Wzh[1024 * NOISE];   // 64 KB
__device__ __align__(16) __nv_bfloat16 g_Wzl[1024 * NOISE];   // 64 KB

// ---------------------------------------------------------------------------
// Prep: split A = [x|feature] into bf16 hi/lo, row-major [2048][2048]
// ---------------------------------------------------------------------------
__global__ __launch_bounds__(256) void convert_split_A(
    const float* __restrict__ X, const float* __restrict__ F) {
    int i4 = blockIdx.x * 256 + threadIdx.x;
    int row = i4 >> 9;
    int c4 = i4 & 511;
    const float* src = (c4 < 256) ? (X + row * 1024 + c4 * 4)
                                  : (F + row * 1024 + (c4 - 256) * 4);
    float4 v = *(const float4*)src;
    __nv_bfloat16 h0 = __float2bfloat16_rn(v.x), h1 = __float2bfloat16_rn(v.y);
    __nv_bfloat16 h2 = __float2bfloat16_rn(v.z), h3 = __float2bfloat16_rn(v.w);
    __nv_bfloat16 l0 = __float2bfloat16_rn(v.x - __bfloat162float(h0));
    __nv_bfloat16 l1 = __float2bfloat16_rn(v.y - __bfloat162float(h1));
    __nv_bfloat16 l2 = __float2bfloat16_rn(v.z - __bfloat162float(h2));
    __nv_bfloat16 l3 = __float2bfloat16_rn(v.w - __bfloat162float(h3));
    __nv_bfloat162 ph0 = __halves2bfloat162(h0, h1), ph1 = __halves2bfloat162(h2, h3);
    __nv_bfloat162 pl0 = __halves2bfloat162(l0, l1), pl1 = __halves2bfloat162(l2, l3);
    uint2 uh; uh.x = *(uint32_t*)&ph0; uh.y = *(uint32_t*)&ph1;
    uint2 ul; ul.x = *(uint32_t*)&pl0; ul.y = *(uint32_t*)&pl1;
    size_t off = (size_t)row * KTOT + c4 * 4;
    *(uint2*)(g_Ahi + off) = uh;
    *(uint2*)(g_Alo + off) = ul;
}

// ---------------------------------------------------------------------------
// Prep: split Z [16384][32] fp32 -> bf16 hi/lo
// ---------------------------------------------------------------------------
__global__ __launch_bounds__(256) void prep_z_split(const float* __restrict__ Z) {
    int i4 = blockIdx.x * 256 + threadIdx.x;   // BN_TOT*NOISE/4 = 131072
    float4 v = *(const float4*)(Z + i4 * 4);
    __nv_bfloat16 h0 = __float2bfloat16_rn(v.x), h1 = __float2bfloat16_rn(v.y);
    __nv_bfloat16 h2 = __float2bfloat16_rn(v.z), h3 = __float2bfloat16_rn(v.w);
    __nv_bfloat16 l0 = __float2bfloat16_rn(v.x - __bfloat162float(h0));
    __nv_bfloat16 l1 = __float2bfloat16_rn(v.y - __bfloat162float(h1));
    __nv_bfloat16 l2 = __float2bfloat16_rn(v.z - __bfloat162float(h2));
    __nv_bfloat16 l3 = __float2bfloat16_rn(v.w - __bfloat162float(h3));
    __nv_bfloat162 ph0 = __halves2bfloat162(h0, h1), ph1 = __halves2bfloat162(h2, h3);
    __nv_bfloat162 pl0 = __halves2bfloat162(l0, l1), pl1 = __halves2bfloat162(l2, l3);
    uint2 uh; uh.x = *(uint32_t*)&ph0; uh.y = *(uint32_t*)&ph1;
    uint2 ul; ul.x = *(uint32_t*)&pl0; ul.y = *(uint32_t*)&pl1;
    *(uint2*)(g_Zhi + (size_t)i4 * 4) = uh;
    *(uint2*)(g_Zlo + (size_t)i4 * 4) = ul;
}

// ---------------------------------------------------------------------------
// Prep: build Wz [1024][32]: rows 0-511 = W1z (Wep1[2048+k][n]), rows 512-1023 = Wep2[n-512][k]
// ---------------------------------------------------------------------------
__global__ __launch_bounds__(256) void prep_wz(
    const float* __restrict__ Wep1, const float* __restrict__ Wep2) {
    int idx = blockIdx.x * 256 + threadIdx.x;   // 32768
    int n = idx >> 5;
    int k = idx & 31;
    float v = (n < 512) ? Wep1[(2048 + k) * EPI_H + n] : Wep2[(n - 512) * NOISE + k];
    __nv_bfloat16 h = __float2bfloat16_rn(v);
    __nv_bfloat16 l = __float2bfloat16_rn(v - __bfloat162float(h));
    g_Wzh[idx] = h;
    g_Wzl[idx] = l;
}

// ---------------------------------------------------------------------------
// Prep: transpose+split W[0:2048][512] -> Bhi/Blo [512][2048]
// ---------------------------------------------------------------------------
__global__ __launch_bounds__(256) void transpose_split_W(const float* __restrict__ W) {
    __shared__ float t[32][33];
    int kt = blockIdx.x;   // 64
    int nt = blockIdx.y;   // 16
    int tx = threadIdx.x;  // 32
    int ty = threadIdx.y;  // 8
#pragma unroll
    for (int i = 0; i < 4; i++)
        t[ty * 4 + i][tx] = W[(size_t)(kt * 32 + ty * 4 + i) * EPI_H + nt * 32 + tx];
    __syncthreads();
#pragma unroll
    for (int i = 0; i < 4; i++) {
        int n = nt * 32 + ty * 4 + i;
        int k = kt * 32 + tx;
        float v = t[tx][ty * 4 + i];
        __nv_bfloat16 h = __float2bfloat16_rn(v);
        __nv_bfloat16 l = __float2bfloat16_rn(v - __bfloat162float(h));
        g_Bhi[(size_t)n * KTOT + k] = h;
        g_Blo[(size_t)n * KTOT + k] = l;
    }
}

// ---------------------------------------------------------------------------
// Repack Wp1[32][1024][5] -> W1r[1024][160]
// ---------------------------------------------------------------------------
__global__ void repack_wp1(const float* __restrict__ Wp1) {
    int idx = blockIdx.x * 256 + threadIdx.x;
    if (idx < STATE * PRI_N) {
        int k = idx / PRI_N;
        int c = idx - k * PRI_N;
        int e = c / PRIOR_H;
        int h = c - e * PRIOR_H;
        g_W1r[idx] = Wp1[e * (STATE * PRIOR_H) + k * PRIOR_H + h];
    }
}

// ---------------------------------------------------------------------------
// Main tensor-core GEMM (unchanged from R11/R12): g_H = A@W + bias
// ---------------------------------------------------------------------------
#define GM_BM 64
#define GM_BN 64
#define GM_BK 64
#define NKB (KTOT / GM_BK)    // 32
#define SM_AHI 0
#define SM_ALO 8192
#define SM_BHI 16384
#define SM_BLO 24576
#define STAGE_B 32768
#define NSTAGE 3
#define GM_THREADS 128

__device__ __forceinline__ uint32_t swz(int r, int c) {
    return (uint32_t)(r * 128 + ((c ^ (r & 7)) * 16));
}
__device__ __forceinline__ void ldmx4(uint32_t addr, uint32_t* r) {
    asm volatile("ldmatrix.sync.aligned.m8n8.x4.shared.b16 {%0,%1,%2,%3}, [%4];"
        : "=r"(r[0]), "=r"(r[1]), "=r"(r[2]), "=r"(r[3]) : "r"(addr));
}
__device__ __forceinline__ void mma16816(float* c, const uint32_t* a,
                                         uint32_t b0, uint32_t b1) {
    asm volatile("mma.sync.aligned.m16n8k16.row.col.f32.bf16.bf16.f32 "
        "{%0,%1,%2,%3},{%4,%5,%6,%7},{%8,%9},{%0,%1,%2,%3};"
        : "+f"(c[0]), "+f"(c[1]), "+f"(c[2]), "+f"(c[3])
        : "r"(a[0]), "r"(a[1]), "r"(a[2]), "r"(a[3]), "r"(b0), "r"(b1));
}

__device__ __forceinline__ void issue_stage(uint32_t nb, int ko, int tid,
                                            int row0, int col0) {
#pragma unroll
    for (int i = 0; i < 4; i++) {
        int ch = tid + i * GM_THREADS;
        int r = ch >> 3, c = ch & 7;
        uint32_t o = swz(r, c);
        CP16(nb + SM_AHI + o, g_Ahi + (row0 + r) * KTOT + ko + c * 8);
        CP16(nb + SM_ALO + o, g_Alo + (row0 + r) * KTOT + ko + c * 8);
        CP16(nb + SM_BHI + o, g_Bhi + (col0 + r) * KTOT + ko + c * 8);
        CP16(nb + SM_BLO + o, g_Blo + (col0 + r) * KTOT + ko + c * 8);
    }
}

__global__ __launch_bounds__(GM_THREADS, 2) void gemm_mma(const float* __restrict__ bias) {
    extern __shared__ char smem_raw[];
    const uint32_t sb = smem_u32(smem_raw);

    const int tid = threadIdx.x;
    const int lane = tid & 31;
    const int wid = tid >> 5;
    const int wm = wid & 1;
    const int wn = wid >> 1;
    const int row0 = blockIdx.y * GM_BM;
    const int col0 = blockIdx.x * GM_BN;
    const int lrow = lane & 15;
    const int chbase = lane >> 4;

    float acc[2][4][4];
#pragma unroll
    for (int mi = 0; mi < 2; mi++)
#pragma unroll
        for (int nf = 0; nf < 4; nf++)
#pragma unroll
            for (int q = 0; q < 4; q++) acc[mi][nf][q] = 0.f;

    issue_stage(sb, 0, tid, row0, col0);
    CP_COMMIT();
    issue_stage(sb + STAGE_B, GM_BK, tid, row0, col0);
    CP_COMMIT();

    int slot = 0;
    for (int kb = 0; kb < NKB; kb++) {
        CP_WAIT1();
        __syncthreads();

        if (kb + 2 < NKB) {
            int s2 = slot + 2; if (s2 >= NSTAGE) s2 -= NSTAGE;
            issue_stage(sb + s2 * STAGE_B, (kb + 2) * GM_BK, tid, row0, col0);
        }
        CP_COMMIT();

        const uint32_t bufb = sb + slot * STAGE_B;
#pragma unroll
        for (int kblk = 0; kblk < 4; kblk++) {
            const int ch = kblk * 2 + chbase;
            uint32_t ah[2][4], al[2][4], bh[2][4], bl[2][4];
#pragma unroll
            for (int mi = 0; mi < 2; mi++) {
                int r = wm * 32 + mi * 16 + lrow;
                uint32_t off = r * 128 + ((ch ^ (r & 7)) * 16);
                ldmx4(bufb + SM_AHI + off, ah[mi]);
                ldmx4(bufb + SM_ALO + off, al[mi]);
            }
#pragma unroll
            for (int ni = 0; ni < 2; ni++) {
                int r = wn * 32 + ni * 16 + lrow;
                uint32_t off = r * 128 + ((ch ^ (r & 7)) * 16);
                ldmx4(bufb + SM_BHI + off, bh[ni]);
                ldmx4(bufb + SM_BLO + off, bl[ni]);
            }
#pragma unroll
            for (int mi = 0; mi < 2; mi++)
#pragma unroll
                for (int ni = 0; ni < 2; ni++)
#pragma unroll
                    for (int s = 0; s < 2; s++) {
                        float* a = acc[mi][ni * 2 + s];
                        mma16816(a, ah[mi], bh[ni][s], bh[ni][s + 2]);
                        mma16816(a, ah[mi], bl[ni][s], bl[ni][s + 2]);
                        mma16816(a, al[mi], bh[ni][s], bh[ni][s + 2]);
                    }
        }
        slot++; if (slot >= NSTAGE) slot = 0;
    }

#pragma unroll
    for (int mi = 0; mi < 2; mi++)
#pragma unroll
        for (int nf = 0; nf < 4; nf++) {
            int r = row0 + wm * 32 + mi * 16 + (lane >> 2);
            int cc = col0 + wn * 32 + nf * 8 + (lane & 3) * 2;
            float2 b2 = *(const float2*)(bias + cc);
            float2 v0, v1;
            v0.x = acc[mi][nf][0] + b2.x; v0.y = acc[mi][nf][1] + b2.y;
            v1.x = acc[mi][nf][2] + b2.x; v1.y = acc[mi][nf][3] + b2.y;
            *(float2*)(g_H + r * EPI_H + cc) = v0;
            *(float2*)(g_H + (r + 8) * EPI_H + cc) = v1;
        }
}

// ---------------------------------------------------------------------------
// Prior GEMM: g_P1[2048][160] = relu(x @ g_W1r + bp1)   (f32x2)
// ---------------------------------------------------------------------------
#define P_BM 64
#define P_BN 32
#define P_BK 16
__global__ __launch_bounds__(128) void sgemm_prior(
    const float* __restrict__ X, const float* __restrict__ bp1) {
    __shared__ float As[2][P_BK][P_BM + 4];
    __shared__ float Bs[2][P_BK][P_BN];

    const int tid = threadIdx.x;
    const int row0 = blockIdx.y * P_BM;
    const int col0 = blockIdx.x * P_BN;

    const int ar = tid >> 2;
    const int ac4 = tid & 3;
    const int bkr = tid >> 3;
    const int bjc = tid & 7;
    const int ty = tid >> 3;
    const int tx = tid & 7;

    u64 acc2[2][4];
#pragma unroll
    for (int i = 0; i < 2; i++)
#pragma unroll
        for (int j = 0; j < 4; j++) acc2[i][j] = 0ULL;

    float4 pa0, pa1, pb;
    {
        int k = ac4 * 4;
        pa0 = *(const float4*)(X + (row0 + ar) * STATE + k);
        pa1 = *(const float4*)(X + (row0 + ar + 32) * STATE + k);
        pb  = *(const float4*)(g_W1r + bkr * PRI_N + col0 + bjc * 4);
    }
    {
        As[0][ac4 * 4 + 0][ar] = pa0.x; As[0][ac4 * 4 + 1][ar] = pa0.y;
        As[0][ac4 * 4 + 2][ar] = pa0.z; As[0][ac4 * 4 + 3][ar] = pa0.w;
        As[0][ac4 * 4 + 0][ar + 32] = pa1.x; As[0][ac4 * 4 + 1][ar + 32] = pa1.y;
        As[0][ac4 * 4 + 2][ar + 32] = pa1.z; As[0][ac4 * 4 + 3][ar + 32] = pa1.w;
        *(float4*)&Bs[0][bkr][bjc * 4] = pb;
    }
    __syncthreads();

    const int NT = STATE / P_BK;
    int buf = 0;
    for (int kt = 0; kt < NT; kt++) {
        if (kt + 1 < NT) {
            int kg = (kt + 1) * P_BK + ac4 * 4;
            pa0 = *(const float4*)(X + (row0 + ar) * STATE + kg);
            pa1 = *(const float4*)(X + (row0 + ar + 32) * STATE + kg);
            pb  = *(const float4*)(g_W1r + ((kt + 1) * P_BK + bkr) * PRI_N + col0 + bjc * 4);
        }
#pragma unroll
        for (int kk = 0; kk < P_BK; kk++) {
            ulonglong2 aa = *(const ulonglong2*)&As[buf][kk][ty * 4];
            float4 rb = *(const float4*)&Bs[buf][kk][tx * 4];
            u64 a2[2] = {aa.x, aa.y};
            u64 bd[4];
            bd[0] = pk2(rb.x, rb.x); bd[1] = pk2(rb.y, rb.y);
            bd[2] = pk2(rb.z, rb.z); bd[3] = pk2(rb.w, rb.w);
#pragma unroll
            for (int i = 0; i < 2; i++)
#pragma unroll
                for (int j = 0; j < 4; j++)
                    acc2[i][j] = fma2(a2[i], bd[j], acc2[i][j]);
        }
        if (kt + 1 < NT) {
            int nb = buf ^ 1;
            As[nb][ac4 * 4 + 0][ar] = pa0.x; As[nb][ac4 * 4 + 1][ar] = pa0.y;
            As[nb][ac4 * 4 + 2][ar] = pa0.z; As[nb][ac4 * 4 + 3][ar] = pa0.w;
            As[nb][ac4 * 4 + 0][ar + 32] = pa1.x; As[nb][ac4 * 4 + 1][ar + 32] = pa1.y;
            As[nb][ac4 * 4 + 2][ar + 32] = pa1.z; As[nb][ac4 * 4 + 3][ar + 32] = pa1.w;
            *(float4*)&Bs[nb][bkr][bjc * 4] = pb;
        }
        __syncthreads();
        buf ^= 1;
    }

    float4 bv = *(const float4*)(bp1 + col0 + tx * 4);
#pragma unroll
    for (int i2 = 0; i2 < 2; i2++) {
        float2 u0 = unpk(acc2[i2][0]), u1 = unpk(acc2[i2][1]);
        float2 u2 = unpk(acc2[i2][2]), u3 = unpk(acc2[i2][3]);
        int r = row0 + ty * 4 + 2 * i2;
        float4 olo, ohi;
        olo.x = fmaxf(u0.x + bv.x, 0.f); olo.y = fmaxf(u1.x + bv.y, 0.f);
        olo.z = fmaxf(u2.x + bv.z, 0.f); olo.w = fmaxf(u3.x + bv.w, 0.f);
        ohi.x = fmaxf(u0.y + bv.x, 0.f); ohi.y = fmaxf(u1.y + bv.y, 0.f);
        ohi.z = fmaxf(u2.y + bv.z, 0.f); ohi.w = fmaxf(u3.y + bv.w, 0.f);
        *(float4*)(g_P1 + r * PRI_N + col0 + tx * 4) = olo;
        *(float4*)(g_P1 + (r + 1) * PRI_N + col0 + tx * 4) = ohi;
    }
}

// ---------------------------------------------------------------------------
// fused_znet: per CTA, 16 bn-rows.
//  GEMM: S[16,1024] = Zmat[16 rows, 32] @ Wz[32, 1024]  (mma, 3-pass bf16 split)
//  Reduce: out[bn] = sum_j relu(H[b,j]+S[r,j])*S[r,512+j] + sum_e sP[b,e]*z[bn,e]
// 256 threads = 8 warps; warp w owns cols w*128..+127 (16 n8-frags).
// ---------------------------------------------------------------------------
#define FZ_SPAD 1028   // padded row stride in words
__global__ __launch_bounds__(256, 2) void fused_znet(
    const float* __restrict__ Z, const float* __restrict__ bep2,
    const float* __restrict__ Wp2, const float* __restrict__ bp2,
    const float* __restrict__ Wp3, const float* __restrict__ bp3,
    float* __restrict__ out) {
    __shared__ float S[16][FZ_SPAD];   // ~65.8 KB
    __shared__ float sP[2][NOISE];

    const int tid = threadIdx.x;
    const int lane = tid & 31;
    const int w = tid >> 5;          // warp 0..7
    const int g = lane >> 2;         // group 0..7
    const int t = lane & 3;
    const int row0 = blockIdx.x * 16;   // bn rows

    // ---- GEMM phase: acc[16 frags][4] ----
    float acc[16][4];
#pragma unroll
    for (int f = 0; f < 16; f++)
#pragma unroll
        for (int q = 0; q < 4; q++) acc[f][q] = 0.f;

#pragma unroll
    for (int pass = 0; pass < 3; pass++) {
        const __nv_bfloat16* Ap = (pass < 2) ? g_Zhi : g_Zlo;
        const __nv_bfloat16* Bp = (pass == 1) ? g_Wzl : g_Wzh;
#pragma unroll
        for (int ks = 0; ks < 2; ks++) {
            const int k0 = ks * 16;
            uint32_t a[4];
            a[0] = *(const uint32_t*)(Ap + (row0 + g) * NOISE + k0 + t * 2);
            a[1] = *(const uint32_t*)(Ap + (row0 + g + 8) * NOISE + k0 + t * 2);
            a[2] = *(const uint32_t*)(Ap + (row0 + g) * NOISE + k0 + 8 + t * 2);
            a[3] = *(const uint32_t*)(Ap + (row0 + g + 8) * NOISE + k0 + 8 + t * 2);
#pragma unroll
            for (int f = 0; f < 16; f++) {
                int n = w * 128 + f * 8 + g;
                uint32_t b0 = *(const uint32_t*)(Bp + n * NOISE + k0 + t * 2);
                uint32_t b1 = *(const uint32_t*)(Bp + n * NOISE + k0 + 8 + t * 2);
                mma16816(acc[f], a, b0, b1);
            }
        }
    }

    // store acc to padded smem (conflict-free: bank = (4r + c) % 32)
#pragma unroll
    for (int f = 0; f < 16; f++) {
        int col = w * 128 + f * 8 + t * 2;
        *(float2*)&S[g][col] = make_float2(acc[f][0], acc[f][1]);
        *(float2*)&S[g + 8][col] = make_float2(acc[f][2], acc[f][3]);
    }

    // prior MLP for the CTA's 2 b values (threads 0..63)
    if (tid < 64) {
        int bl = tid >> 5;           // 0..1
        int e = tid & 31;
        int b = (row0 >> 3) + bl;
        const float* p1 = g_P1 + b * PRI_N + e * PRIOR_H;
        float h1[PRIOR_H];
#pragma unroll
        for (int h = 0; h < PRIOR_H; h++) h1[h] = p1[h];
        float h2[PRIOR_H];
#pragma unroll
        for (int gg = 0; gg < PRIOR_H; gg++) {
            float s = bp2[e * PRIOR_H + gg];
#pragma unroll
            for (int h = 0; h < PRIOR_H; h++)
                s = fmaf(h1[h], Wp2[e * 25 + h * PRIOR_H + gg], s);
            h2[gg] = fmaxf(s, 0.f);
        }
        float p = bp3[e];
#pragma unroll
        for (int gg = 0; gg < PRIOR_H; gg++)
            p = fmaf(h2[gg], Wp3[e * PRIOR_H + gg], p);
        sP[bl][e] = p + bep2[e];
    }
    __syncthreads();

    // ---- reduce phase: warp w handles rows w and w+8 ----
#pragma unroll
    for (int half = 0; half < 2; half++) {
        const int r = w + half * 8;
        const int bn = row0 + r;
        const int b = bn >> 3;
        const float* Hrow = g_H + (size_t)b * EPI_H;
        float s = 0.f;
#pragma unroll
        for (int i = 0; i < 16; i++) {
            int j = i * 32 + lane;
            float hz = S[r][j];
            float wz = S[r][512 + j];
            s = fmaf(fmaxf(Hrow[j] + hz, 0.f), wz, s);
        }
        // prior contribution: lane e
        s = fmaf(sP[(bn >> 3) & 1 ? ((bn >> 3) - (row0 >> 3)) : ((bn >> 3) - (row0 >> 3))][lane],
                 Z[(size_t)bn * NOISE + lane], s);
        // warp reduce
        s += __shfl_xor_sync(0xffffffffu, s, 16);
        s += __shfl_xor_sync(0xffffffffu, s, 8);
        s += __shfl_xor_sync(0xffffffffu, s, 4);
        s += __shfl_xor_sync(0xffffffffu, s, 2);
        s += __shfl_xor_sync(0xffffffffu, s, 1);
        if (lane == 0) out[bn] = s;
    }
}

// ---------------------------------------------------------------------------
extern "C" void kernel_launch(void* const* d_in, const int* in_sizes, int n_in,
                              void* d_out, int out_size) {
    const float* x    = (const float*)d_in[0];
    const float* feat = (const float*)d_in[1];
    const float* z    = (const float*)d_in[2];
    const float* Wep1 = (const float*)d_in[3];
    const float* bep1 = (const float*)d_in[4];
    const float* Wep2 = (const float*)d_in[5];
    const float* bep2 = (const float*)d_in[6];
    const float* Wp1  = (const float*)d_in[7];
    const float* bp1  = (const float*)d_in[8];
    const float* Wp2  = (const float*)d_in[9];
    const float* bp2  = (const float*)d_in[10];
    const float* Wp3  = (const float*)d_in[11];
    const float* bp3  = (const float*)d_in[12];
    float* out = (float*)d_out;

    cudaFuncSetAttribute(gemm_mma, cudaFuncAttributeMaxDynamicSharedMemorySize,
                         NSTAGE * STAGE_B);

    convert_split_A<<<(B_DIM * KTOT / 4) / 256, 256>>>(x, feat);
    transpose_split_W<<<dim3(64, 16), dim3(32, 8)>>>(Wep1);
    repack_wp1<<<(STATE * PRI_N + 255) / 256, 256>>>(Wp1);
    prep_z_split<<<(BN_TOT * NOISE / 4) / 256, 256>>>(z);
    prep_wz<<<(1024 * NOISE) / 256, 256>>>(Wep1, Wep2);
    gemm_mma<<<dim3(EPI_H / GM_BN, B_DIM / GM_BM), GM_THREADS, NSTAGE * STAGE_B>>>(bep1);
    sgemm_prior<<<dim3(PRI_N / P_BN, B_DIM / P_BM), 128>>>(x, bp1);
    fused_znet<<<BN_TOT / 16, 256>>>(z, bep2, Wp2, bp2, Wp3, bp3, out);
}

// round 16
// speedup vs baseline: 1.1919x; 1.0853x over previous
#include <cuda_runtime.h>
#include <cuda_bf16.h>
#include <cstdint>

// Shapes
#define B_DIM 2048
#define N_Z 8
#define NOISE 32
#define STATE 1024
#define HID 1024
#define EPI_H 512
#define PRIOR_H 5
#define PRI_N 160   // 32 ensembles * 5
#define KTOT 2048   // xf concat length
#define BN_TOT (B_DIM * N_Z)   // 16384

typedef unsigned long long u64;

// ---- f32x2 helpers (prior gemm) ----
__device__ __forceinline__ u64 pk2(float lo, float hi) {
    u64 r; asm("mov.b64 %0,{%1,%2};" : "=l"(r) : "f"(lo), "f"(hi)); return r;
}
__device__ __forceinline__ u64 fma2(u64 a, u64 b, u64 c) {
    u64 d; asm("fma.rn.f32x2 %0,%1,%2,%3;" : "=l"(d) : "l"(a), "l"(b), "l"(c)); return d;
}
__device__ __forceinline__ float2 unpk(u64 v) {
    float2 r; asm("mov.b64 {%0,%1},%2;" : "=f"(r.x), "=f"(r.y) : "l"(v)); return r;
}

__device__ __forceinline__ uint32_t smem_u32(const void* p) {
    uint32_t a;
    asm("{ .reg .u64 t; cvta.to.shared.u64 t, %1; cvt.u32.u64 %0, t; }" : "=r"(a) : "l"(p));
    return a;
}

// ---- cp.async ----
#define CP16(dst, src) \
    asm volatile("cp.async.cg.shared.global [%0], [%1], 16;" :: "r"(dst), "l"(src))
#define CP_COMMIT() asm volatile("cp.async.commit_group;" ::: "memory")
#define CP_WAIT1() asm volatile("cp.async.wait_group 1;" ::: "memory")

// ---- Scratch (no allocation allowed) ----
__device__ float g_H[B_DIM * EPI_H];
__device__ float g_P1[B_DIM * PRI_N];
__device__ float g_W1r[STATE * PRI_N];
__device__ __align__(16) __nv_bfloat16 g_Ahi[B_DIM * KTOT];   // 8 MB
__device__ __align__(16) __nv_bfloat16 g_Alo[B_DIM * KTOT];   // 8 MB
__device__ __align__(16) __nv_bfloat16 g_Bhi[EPI_H * KTOT];   // 2 MB
__device__ __align__(16) __nv_bfloat16 g_Blo[EPI_H * KTOT];   // 2 MB
__device__ __align__(16) __nv_bfloat16 g_Zhi[BN_TOT * NOISE]; // 1 MB
__device__ __align__(16) __nv_bfloat16 g_Zlo[BN_TOT * NOISE]; // 1 MB
__device__ __align__(16) __nv_bfloat16 g_Wzh[1024 * NOISE];   // 64 KB (interleaved)
__device__ __align__(16) __nv_bfloat16 g_Wzl[1024 * NOISE];   // 64 KB (interleaved)

// ---------------------------------------------------------------------------
// Prep: split A = [x|feature] into bf16 hi/lo, row-major [2048][2048]
// ---------------------------------------------------------------------------
__global__ __launch_bounds__(256) void convert_split_A(
    const float* __restrict__ X, const float* __restrict__ F) {
    int i4 = blockIdx.x * 256 + threadIdx.x;
    int row = i4 >> 9;
    int c4 = i4 & 511;
    const float* src = (c4 < 256) ? (X + row * 1024 + c4 * 4)
                                  : (F + row * 1024 + (c4 - 256) * 4);
    float4 v = *(const float4*)src;
    __nv_bfloat16 h0 = __float2bfloat16_rn(v.x), h1 = __float2bfloat16_rn(v.y);
    __nv_bfloat16 h2 = __float2bfloat16_rn(v.z), h3 = __float2bfloat16_rn(v.w);
    __nv_bfloat16 l0 = __float2bfloat16_rn(v.x - __bfloat162float(h0));
    __nv_bfloat16 l1 = __float2bfloat16_rn(v.y - __bfloat162float(h1));
    __nv_bfloat16 l2 = __float2bfloat16_rn(v.z - __bfloat162float(h2));
    __nv_bfloat16 l3 = __float2bfloat16_rn(v.w - __bfloat162float(h3));
    __nv_bfloat162 ph0 = __halves2bfloat162(h0, h1), ph1 = __halves2bfloat162(h2, h3);
    __nv_bfloat162 pl0 = __halves2bfloat162(l0, l1), pl1 = __halves2bfloat162(l2, l3);
    uint2 uh; uh.x = *(uint32_t*)&ph0; uh.y = *(uint32_t*)&ph1;
    uint2 ul; ul.x = *(uint32_t*)&pl0; ul.y = *(uint32_t*)&pl1;
    size_t off = (size_t)row * KTOT + c4 * 4;
    *(uint2*)(g_Ahi + off) = uh;
    *(uint2*)(g_Alo + off) = ul;
}

// ---------------------------------------------------------------------------
// Prep: split Z [16384][32] fp32 -> bf16 hi/lo
// ---------------------------------------------------------------------------
__global__ __launch_bounds__(256) void prep_z_split(const float* __restrict__ Z) {
    int i4 = blockIdx.x * 256 + threadIdx.x;
    float4 v = *(const float4*)(Z + i4 * 4);
    __nv_bfloat16 h0 = __float2bfloat16_rn(v.x), h1 = __float2bfloat16_rn(v.y);
    __nv_bfloat16 h2 = __float2bfloat16_rn(v.z), h3 = __float2bfloat16_rn(v.w);
    __nv_bfloat16 l0 = __float2bfloat16_rn(v.x - __bfloat162float(h0));
    __nv_bfloat16 l1 = __float2bfloat16_rn(v.y - __bfloat162float(h1));
    __nv_bfloat16 l2 = __float2bfloat16_rn(v.z - __bfloat162float(h2));
    __nv_bfloat16 l3 = __float2bfloat16_rn(v.w - __bfloat162float(h3));
    __nv_bfloat162 ph0 = __halves2bfloat162(h0, h1), ph1 = __halves2bfloat162(h2, h3);
    __nv_bfloat162 pl0 = __halves2bfloat162(l0, l1), pl1 = __halves2bfloat162(l2, l3);
    uint2 uh; uh.x = *(uint32_t*)&ph0; uh.y = *(uint32_t*)&ph1;
    uint2 ul; ul.x = *(uint32_t*)&pl0; ul.y = *(uint32_t*)&pl1;
    *(uint2*)(g_Zhi + (size_t)i4 * 4) = uh;
    *(uint2*)(g_Zlo + (size_t)i4 * 4) = ul;
}

// ---------------------------------------------------------------------------
// Prep: interleaved Wz2 [1024][32]: row 2j = W1z[:,j] (Wep1[2048+k][j]),
//                                   row 2j+1 = Wep2[j][k]
// ---------------------------------------------------------------------------
__global__ __launch_bounds__(256) void prep_wz(
    const float* __restrict__ Wep1, const float* __restrict__ Wep2) {
    int idx = blockIdx.x * 256 + threadIdx.x;   // 32768
    int n = idx >> 5;
    int k = idx & 31;
    int j = n >> 1;
    float v = (n & 1) ? Wep2[j * NOISE + k] : Wep1[(2048 + k) * EPI_H + j];
    __nv_bfloat16 h = __float2bfloat16_rn(v);
    __nv_bfloat16 l = __float2bfloat16_rn(v - __bfloat162float(h));
    g_Wzh[idx] = h;
    g_Wzl[idx] = l;
}

// ---------------------------------------------------------------------------
// Prep: transpose+split W[0:2048][512] -> Bhi/Blo [512][2048]
// ---------------------------------------------------------------------------
__global__ __launch_bounds__(256) void transpose_split_W(const float* __restrict__ W) {
    __shared__ float t[32][33];
    int kt = blockIdx.x;
    int nt = blockIdx.y;
    int tx = threadIdx.x;
    int ty = threadIdx.y;
#pragma unroll
    for (int i = 0; i < 4; i++)
        t[ty * 4 + i][tx] = W[(size_t)(kt * 32 + ty * 4 + i) * EPI_H + nt * 32 + tx];
    __syncthreads();
#pragma unroll
    for (int i = 0; i < 4; i++) {
        int n = nt * 32 + ty * 4 + i;
        int k = kt * 32 + tx;
        float v = t[tx][ty * 4 + i];
        __nv_bfloat16 h = __float2bfloat16_rn(v);
        __nv_bfloat16 l = __float2bfloat16_rn(v - __bfloat162float(h));
        g_Bhi[(size_t)n * KTOT + k] = h;
        g_Blo[(size_t)n * KTOT + k] = l;
    }
}

// ---------------------------------------------------------------------------
// Repack Wp1[32][1024][5] -> W1r[1024][160]
// ---------------------------------------------------------------------------
__global__ void repack_wp1(const float* __restrict__ Wp1) {
    int idx = blockIdx.x * 256 + threadIdx.x;
    if (idx < STATE * PRI_N) {
        int k = idx / PRI_N;
        int c = idx - k * PRI_N;
        int e = c / PRIOR_H;
        int h = c - e * PRIOR_H;
        g_W1r[idx] = Wp1[e * (STATE * PRIOR_H) + k * PRIOR_H + h];
    }
}

// ---------------------------------------------------------------------------
// Main tensor-core GEMM (unchanged): g_H = A@W + bias
// ---------------------------------------------------------------------------
#define GM_BM 64
#define GM_BN 64
#define GM_BK 64
#define NKB (KTOT / GM_BK)
#define SM_AHI 0
#define SM_ALO 8192
#define SM_BHI 16384
#define SM_BLO 24576
#define STAGE_B 32768
#define NSTAGE 3
#define GM_THREADS 128

__device__ __forceinline__ uint32_t swz(int r, int c) {
    return (uint32_t)(r * 128 + ((c ^ (r & 7)) * 16));
}
__device__ __forceinline__ void ldmx4(uint32_t addr, uint32_t* r) {
    asm volatile("ldmatrix.sync.aligned.m8n8.x4.shared.b16 {%0,%1,%2,%3}, [%4];"
        : "=r"(r[0]), "=r"(r[1]), "=r"(r[2]), "=r"(r[3]) : "r"(addr));
}
__device__ __forceinline__ void mma16816(float* c, const uint32_t* a,
                                         uint32_t b0, uint32_t b1) {
    asm volatile("mma.sync.aligned.m16n8k16.row.col.f32.bf16.bf16.f32 "
        "{%0,%1,%2,%3},{%4,%5,%6,%7},{%8,%9},{%0,%1,%2,%3};"
        : "+f"(c[0]), "+f"(c[1]), "+f"(c[2]), "+f"(c[3])
        : "r"(a[0]), "r"(a[1]), "r"(a[2]), "r"(a[3]), "r"(b0), "r"(b1));
}

__device__ __forceinline__ void issue_stage(uint32_t nb, int ko, int tid,
                                            int row0, int col0) {
#pragma unroll
    for (int i = 0; i < 4; i++) {
        int ch = tid + i * GM_THREADS;
        int r = ch >> 3, c = ch & 7;
        uint32_t o = swz(r, c);
        CP16(nb + SM_AHI + o, g_Ahi + (row0 + r) * KTOT + ko + c * 8);
        CP16(nb + SM_ALO + o, g_Alo + (row0 + r) * KTOT + ko + c * 8);
        CP16(nb + SM_BHI + o, g_Bhi + (col0 + r) * KTOT + ko + c * 8);
        CP16(nb + SM_BLO + o, g_Blo + (col0 + r) * KTOT + ko + c * 8);
    }
}

__global__ __launch_bounds__(GM_THREADS, 2) void gemm_mma(const float* __restrict__ bias) {
    extern __shared__ char smem_raw[];
    const uint32_t sb = smem_u32(smem_raw);

    const int tid = threadIdx.x;
    const int lane = tid & 31;
    const int wid = tid >> 5;
    const int wm = wid & 1;
    const int wn = wid >> 1;
    const int row0 = blockIdx.y * GM_BM;
    const int col0 = blockIdx.x * GM_BN;
    const int lrow = lane & 15;
    const int chbase = lane >> 4;

    float acc[2][4][4];
#pragma unroll
    for (int mi = 0; mi < 2; mi++)
#pragma unroll
        for (int nf = 0; nf < 4; nf++)
#pragma unroll
            for (int q = 0; q < 4; q++) acc[mi][nf][q] = 0.f;

    issue_stage(sb, 0, tid, row0, col0);
    CP_COMMIT();
    issue_stage(sb + STAGE_B, GM_BK, tid, row0, col0);
    CP_COMMIT();

    int slot = 0;
    for (int kb = 0; kb < NKB; kb++) {
        CP_WAIT1();
        __syncthreads();

        if (kb + 2 < NKB) {
            int s2 = slot + 2; if (s2 >= NSTAGE) s2 -= NSTAGE;
            issue_stage(sb + s2 * STAGE_B, (kb + 2) * GM_BK, tid, row0, col0);
        }
        CP_COMMIT();

        const uint32_t bufb = sb + slot * STAGE_B;
#pragma unroll
        for (int kblk = 0; kblk < 4; kblk++) {
            const int ch = kblk * 2 + chbase;
            uint32_t ah[2][4], al[2][4], bh[2][4], bl[2][4];
#pragma unroll
            for (int mi = 0; mi < 2; mi++) {
                int r = wm * 32 + mi * 16 + lrow;
                uint32_t off = r * 128 + ((ch ^ (r & 7)) * 16);
                ldmx4(bufb + SM_AHI + off, ah[mi]);
                ldmx4(bufb + SM_ALO + off, al[mi]);
            }
#pragma unroll
            for (int ni = 0; ni < 2; ni++) {
                int r = wn * 32 + ni * 16 + lrow;
                uint32_t off = r * 128 + ((ch ^ (r & 7)) * 16);
                ldmx4(bufb + SM_BHI + off, bh[ni]);
                ldmx4(bufb + SM_BLO + off, bl[ni]);
            }
#pragma unroll
            for (int mi = 0; mi < 2; mi++)
#pragma unroll
                for (int ni = 0; ni < 2; ni++)
#pragma unroll
                    for (int s = 0; s < 2; s++) {
                        float* a = acc[mi][ni * 2 + s];
                        mma16816(a, ah[mi], bh[ni][s], bh[ni][s + 2]);
                        mma16816(a, ah[mi], bl[ni][s], bl[ni][s + 2]);
                        mma16816(a, al[mi], bh[ni][s], bh[ni][s + 2]);
                    }
        }
        slot++; if (slot >= NSTAGE) slot = 0;
    }

#pragma unroll
    for (int mi = 0; mi < 2; mi++)
#pragma unroll
        for (int nf = 0; nf < 4; nf++) {
            int r = row0 + wm * 32 + mi * 16 + (lane >> 2);
            int cc = col0 + wn * 32 + nf * 8 + (lane & 3) * 2;
            float2 b2 = *(const float2*)(bias + cc);
            float2 v0, v1;
            v0.x = acc[mi][nf][0] + b2.x; v0.y = acc[mi][nf][1] + b2.y;
            v1.x = acc[mi][nf][2] + b2.x; v1.y = acc[mi][nf][3] + b2.y;
            *(float2*)(g_H + r * EPI_H + cc) = v0;
            *(float2*)(g_H + (r + 8) * EPI_H + cc) = v1;
        }
}

// ---------------------------------------------------------------------------
// Prior GEMM: g_P1[2048][160] = relu(x @ g_W1r + bp1)   (f32x2)
// ---------------------------------------------------------------------------
#define P_BM 64
#define P_BN 32
#define P_BK 16
__global__ __launch_bounds__(128) void sgemm_prior(
    const float* __restrict__ X, const float* __restrict__ bp1) {
    __shared__ float As[2][P_BK][P_BM + 4];
    __shared__ float Bs[2][P_BK][P_BN];

    const int tid = threadIdx.x;
    const int row0 = blockIdx.y * P_BM;
    const int col0 = blockIdx.x * P_BN;

    const int ar = tid >> 2;
    const int ac4 = tid & 3;
    const int bkr = tid >> 3;
    const int bjc = tid & 7;
    const int ty = tid >> 3;
    const int tx = tid & 7;

    u64 acc2[2][4];
#pragma unroll
    for (int i = 0; i < 2; i++)
#pragma unroll
        for (int j = 0; j < 4; j++) acc2[i][j] = 0ULL;

    float4 pa0, pa1, pb;
    {
        int k = ac4 * 4;
        pa0 = *(const float4*)(X + (row0 + ar) * STATE + k);
        pa1 = *(const float4*)(X + (row0 + ar + 32) * STATE + k);
        pb  = *(const float4*)(g_W1r + bkr * PRI_N + col0 + bjc * 4);
    }
    {
        As[0][ac4 * 4 + 0][ar] = pa0.x; As[0][ac4 * 4 + 1][ar] = pa0.y;
        As[0][ac4 * 4 + 2][ar] = pa0.z; As[0][ac4 * 4 + 3][ar] = pa0.w;
        As[0][ac4 * 4 + 0][ar + 32] = pa1.x; As[0][ac4 * 4 + 1][ar + 32] = pa1.y;
        As[0][ac4 * 4 + 2][ar + 32] = pa1.z; As[0][ac4 * 4 + 3][ar + 32] = pa1.w;
        *(float4*)&Bs[0][bkr][bjc * 4] = pb;
    }
    __syncthreads();

    const int NT = STATE / P_BK;
    int buf = 0;
    for (int kt = 0; kt < NT; kt++) {
        if (kt + 1 < NT) {
            int kg = (kt + 1) * P_BK + ac4 * 4;
            pa0 = *(const float4*)(X + (row0 + ar) * STATE + kg);
            pa1 = *(const float4*)(X + (row0 + ar + 32) * STATE + kg);
            pb  = *(const float4*)(g_W1r + ((kt + 1) * P_BK + bkr) * PRI_N + col0 + bjc * 4);
        }
#pragma unroll
        for (int kk = 0; kk < P_BK; kk++) {
            ulonglong2 aa = *(const ulonglong2*)&As[buf][kk][ty * 4];
            float4 rb = *(const float4*)&Bs[buf][kk][tx * 4];
            u64 a2[2] = {aa.x, aa.y};
            u64 bd[4];
            bd[0] = pk2(rb.x, rb.x); bd[1] = pk2(rb.y, rb.y);
            bd[2] = pk2(rb.z, rb.z); bd[3] = pk2(rb.w, rb.w);
#pragma unroll
            for (int i = 0; i < 2; i++)
#pragma unroll
                for (int j = 0; j < 4; j++)
                    acc2[i][j] = fma2(a2[i], bd[j], acc2[i][j]);
        }
        if (kt + 1 < NT) {
            int nb = buf ^ 1;
            As[nb][ac4 * 4 + 0][ar] = pa0.x; As[nb][ac4 * 4 + 1][ar] = pa0.y;
            As[nb][ac4 * 4 + 2][ar] = pa0.z; As[nb][ac4 * 4 + 3][ar] = pa0.w;
            As[nb][ac4 * 4 + 0][ar + 32] = pa1.x; As[nb][ac4 * 4 + 1][ar + 32] = pa1.y;
            As[nb][ac4 * 4 + 2][ar + 32] = pa1.z; As[nb][ac4 * 4 + 3][ar + 32] = pa1.w;
            *(float4*)&Bs[nb][bkr][bjc * 4] = pb;
        }
        __syncthreads();
        buf ^= 1;
    }

    float4 bv = *(const float4*)(bp1 + col0 + tx * 4);
#pragma unroll
    for (int i2 = 0; i2 < 2; i2++) {
        float2 u0 = unpk(acc2[i2][0]), u1 = unpk(acc2[i2][1]);
        float2 u2 = unpk(acc2[i2][2]), u3 = unpk(acc2[i2][3]);
        int r = row0 + ty * 4 + 2 * i2;
        float4 olo, ohi;
        olo.x = fmaxf(u0.x + bv.x, 0.f); olo.y = fmaxf(u1.x + bv.y, 0.f);
        olo.z = fmaxf(u2.x + bv.z, 0.f); olo.w = fmaxf(u3.x + bv.w, 0.f);
        ohi.x = fmaxf(u0.y + bv.x, 0.f); ohi.y = fmaxf(u1.y + bv.y, 0.f);
        ohi.z = fmaxf(u2.y + bv.z, 0.f); ohi.w = fmaxf(u3.y + bv.w, 0.f);
        *(float4*)(g_P1 + r * PRI_N + col0 + tx * 4) = olo;
        *(float4*)(g_P1 + (r + 1) * PRI_N + col0 + tx * 4) = ohi;
    }
}

// ---------------------------------------------------------------------------
// fused_znet (v2, interleaved Wz2): per CTA, 16 bn-rows (= 2 b values).
// MMA over Wz2[1024][32] whose col pairs (2j,2j+1) = (hz_j, wz_j) land in the
// SAME lane's register pair -> fused relu-dot in registers, no S-buffer.
// ---------------------------------------------------------------------------
__global__ __launch_bounds__(256, 2) void fused_znet(
    const float* __restrict__ Z, const float* __restrict__ bep2,
    const float* __restrict__ Wp2, const float* __restrict__ bp2,
    const float* __restrict__ Wp3, const float* __restrict__ bp3,
    float* __restrict__ out) {
    __shared__ __align__(16) float sH[2][EPI_H];   // 4 KB
    __shared__ float sP[2][NOISE];
    __shared__ float sOut[16][8];

    const int tid = threadIdx.x;
    const int lane = tid & 31;
    const int w = tid >> 5;          // warp 0..7 -> j range w*64..+63
    const int g = lane >> 2;         // 0..7
    const int t = lane & 3;
    const int row0 = blockIdx.x * 16;
    const int b0 = row0 >> 3;        // two consecutive b

    // stage H rows for both b (float4 per thread)
    {
        int half = tid >> 7;         // 0..1
        int i = (tid & 127) * 4;
        *(float4*)&sH[half][i] = *(const float4*)(g_H + (size_t)(b0 + half) * EPI_H + i);
    }
    // prior MLP (threads 0..63)
    if (tid < 64) {
        int bl = tid >> 5;
        int e = tid & 31;
        const float* p1 = g_P1 + (b0 + bl) * PRI_N + e * PRIOR_H;
        float h1[PRIOR_H];
#pragma unroll
        for (int h = 0; h < PRIOR_H; h++) h1[h] = p1[h];
        float h2[PRIOR_H];
#pragma unroll
        for (int gg = 0; gg < PRIOR_H; gg++) {
            float s = bp2[e * PRIOR_H + gg];
#pragma unroll
            for (int h = 0; h < PRIOR_H; h++)
                s = fmaf(h1[h], Wp2[e * 25 + h * PRIOR_H + gg], s);
            h2[gg] = fmaxf(s, 0.f);
        }
        float p = bp3[e];
#pragma unroll
        for (int gg = 0; gg < PRIOR_H; gg++)
            p = fmaf(h2[gg], Wp3[e * PRIOR_H + gg], p);
        sP[bl][e] = p + bep2[e];
    }

    // ---- GEMM: c[16][4], 3-pass split, bh reused for passes 0 & 2 ----
    float c[16][4];
#pragma unroll
    for (int f = 0; f < 16; f++)
#pragma unroll
        for (int q = 0; q < 4; q++) c[f][q] = 0.f;

#pragma unroll
    for (int ks = 0; ks < 2; ks++) {
        const int k0 = ks * 16;
        uint32_t ahi[4], alo[4];
        ahi[0] = *(const uint32_t*)(g_Zhi + (row0 + g) * NOISE + k0 + t * 2);
        ahi[1] = *(const uint32_t*)(g_Zhi + (row0 + g + 8) * NOISE + k0 + t * 2);
        ahi[2] = *(const uint32_t*)(g_Zhi + (row0 + g) * NOISE + k0 + 8 + t * 2);
        ahi[3] = *(const uint32_t*)(g_Zhi + (row0 + g + 8) * NOISE + k0 + 8 + t * 2);
        alo[0] = *(const uint32_t*)(g_Zlo + (row0 + g) * NOISE + k0 + t * 2);
        alo[1] = *(const uint32_t*)(g_Zlo + (row0 + g + 8) * NOISE + k0 + t * 2);
        alo[2] = *(const uint32_t*)(g_Zlo + (row0 + g) * NOISE + k0 + 8 + t * 2);
        alo[3] = *(const uint32_t*)(g_Zlo + (row0 + g + 8) * NOISE + k0 + 8 + t * 2);
#pragma unroll
        for (int f = 0; f < 16; f++) {
            int n = w * 128 + f * 8 + g;
            uint32_t bh0 = *(const uint32_t*)(g_Wzh + n * NOISE + k0 + t * 2);
            uint32_t bh1 = *(const uint32_t*)(g_Wzh + n * NOISE + k0 + 8 + t * 2);
            uint32_t bl0 = *(const uint32_t*)(g_Wzl + n * NOISE + k0 + t * 2);
            uint32_t bl1 = *(const uint32_t*)(g_Wzl + n * NOISE + k0 + 8 + t * 2);
            mma16816(c[f], ahi, bh0, bh1);   // Zhi * Wzh
            mma16816(c[f], ahi, bl0, bl1);   // Zhi * Wzl
            mma16816(c[f], alo, bh0, bh1);   // Zlo * Wzh
        }
    }
    __syncthreads();   // sH / sP ready

    // ---- fused reduce in registers ----
    float s0 = 0.f, s1 = 0.f;
#pragma unroll
    for (int f = 0; f < 16; f++) {
        int j = (w << 6) + (f << 2) + t;
        float h0 = sH[0][j], h1 = sH[1][j];
        s0 = fmaf(fmaxf(h0 + c[f][0], 0.f), c[f][1], s0);
        s1 = fmaf(fmaxf(h1 + c[f][2], 0.f), c[f][3], s1);
    }
    s0 += __shfl_xor_sync(0xffffffffu, s0, 1);
    s0 += __shfl_xor_sync(0xffffffffu, s0, 2);
    s1 += __shfl_xor_sync(0xffffffffu, s1, 1);
    s1 += __shfl_xor_sync(0xffffffffu, s1, 2);
    if (t == 0) {
        sOut[g][w] = s0;
        sOut[g + 8][w] = s1;
    }
    __syncthreads();

    if (tid < 16) {
        float s = 0.f;
#pragma unroll
        for (int ww = 0; ww < 8; ww++) s += sOut[tid][ww];
        const float* zr = Z + (size_t)(row0 + tid) * NOISE;
        const float* pr = sP[tid >> 3];
#pragma unroll
        for (int e4 = 0; e4 < NOISE / 4; e4++) {
            float4 zv = *(const float4*)(zr + e4 * 4);
            s = fmaf(pr[e4 * 4 + 0], zv.x, s);
            s = fmaf(pr[e4 * 4 + 1], zv.y, s);
            s = fmaf(pr[e4 * 4 + 2], zv.z, s);
            s = fmaf(pr[e4 * 4 + 3], zv.w, s);
        }
        out[row0 + tid] = s;
    }
}

// ---------------------------------------------------------------------------
extern "C" void kernel_launch(void* const* d_in, const int* in_sizes, int n_in,
                              void* d_out, int out_size) {
    const float* x    = (const float*)d_in[0];
    const float* feat = (const float*)d_in[1];
    const float* z    = (const float*)d_in[2];
    const float* Wep1 = (const float*)d_in[3];
    const float* bep1 = (const float*)d_in[4];
    const float* Wep2 = (const float*)d_in[5];
    const float* bep2 = (const float*)d_in[6];
    const float* Wp1  = (const float*)d_in[7];
    const float* bp1  = (const float*)d_in[8];
    const float* Wp2  = (const float*)d_in[9];
    const float* bp2  = (const float*)d_in[10];
    const float* Wp3  = (const float*)d_in[11];
    const float* bp3  = (const float*)d_in[12];
    float* out = (float*)d_out;

    cudaFuncSetAttribute(gemm_mma, cudaFuncAttributeMaxDynamicSharedMemorySize,
                         NSTAGE * STAGE_B);

    convert_split_A<<<(B_DIM * KTOT / 4) / 256, 256>>>(x, feat);
    transpose_split_W<<<dim3(64, 16), dim3(32, 8)>>>(Wep1);
    repack_wp1<<<(STATE * PRI_N + 255) / 256, 256>>>(Wp1);
    prep_z_split<<<(BN_TOT * NOISE / 4) / 256, 256>>>(z);
    prep_wz<<<(1024 * NOISE) / 256, 256>>>(Wep1, Wep2);
    gemm_mma<<<dim3(EPI_H / GM_BN, B_DIM / GM_BM), GM_THREADS, NSTAGE * STAGE_B>>>(bep1);
    sgemm_prior<<<dim3(PRI_N / P_BN, B_DIM / P_BM), 128>>>(x, bp1);
    fused_znet<<<BN_TOT / 16, 256>>>(z, bep2, Wp2, bp2, Wp3, bp3, out);
}